// round 17
// baseline (speedup 1.0000x reference)
#include <cuda_runtime.h>
#include <cuda_fp16.h>
#include <math.h>
#include <stdint.h>

// ---------------------------------------------------------------------------
// Problem constants
// ---------------------------------------------------------------------------
#define NB   32
#define NL   4096
#define NH   512
#define NC   1025
#define MTOT (NB * NL)   // 131072

#define MT   128         // m rows per CTA
#define NST  16          // 4 h-tiles x 4 k-stages of 128

// SMEM layout
#define A_ROWB 1040                    // 512 fp16 + 16B pad
#define SM_A   0
#define A_BYTES (128 * A_ROWB)         // 133120
#define B_ROWB 272                     // 128 fp16 + 16B pad
#define B_TILE (128 * B_ROWB)          // 34816
#define SM_B   A_BYTES
#define SM_TAB (A_BYTES + 2 * B_TILE)  // 202752
// tables: w2[512] base[512] wcov[512] red[512]
#define SMEM_TOTAL (SM_TAB + 8192)     // 210944

// ---------------------------------------------------------------------------
// Device scratch (static; no runtime allocation)
// ---------------------------------------------------------------------------
__device__ float g_base[NB * NH];
__device__ float g_logits[MTOT];
__device__ __half g_Bf[NH * 512];             // W1[:,0:512] fp16
__device__ __half g_Af[(size_t)MTOT * 512];   // fp16 ts (side-written by GEMM)
__device__ float g_ctx_part[32 * NB * 512];
__device__ int g_work[1024];                  // compacted (b<<5)|tile list
__device__ int g_nwork;

// ---------------------------------------------------------------------------
// helpers
// ---------------------------------------------------------------------------
__device__ __forceinline__ uint32_t smem_u32(const void* p) {
    uint32_t a;
    asm("{ .reg .u64 t; cvta.to.shared.u64 t, %1; cvt.u32.u64 %0, t; }"
        : "=r"(a) : "l"(p));
    return a;
}

__device__ __forceinline__ void ldsm4(uint32_t addr, uint32_t& r0, uint32_t& r1,
                                      uint32_t& r2, uint32_t& r3) {
    asm volatile("ldmatrix.sync.aligned.m8n8.x4.shared.b16 {%0,%1,%2,%3}, [%4];"
                 : "=r"(r0), "=r"(r1), "=r"(r2), "=r"(r3) : "r"(addr));
}

__device__ __forceinline__ void mma16816(float* d, uint32_t a0, uint32_t a1,
                                         uint32_t a2, uint32_t a3, uint32_t b0,
                                         uint32_t b1) {
    asm volatile(
        "mma.sync.aligned.m16n8k16.row.col.f32.f16.f16.f32 "
        "{%0,%1,%2,%3}, {%4,%5,%6,%7}, {%8,%9}, {%0,%1,%2,%3};"
        : "+f"(d[0]), "+f"(d[1]), "+f"(d[2]), "+f"(d[3])
        : "r"(a0), "r"(a1), "r"(a2), "r"(a3), "r"(b0), "r"(b1));
}

__device__ __forceinline__ void cpasync16(uint32_t dst, const void* src) {
    asm volatile("cp.async.cg.shared.global [%0], [%1], 16;"
                 :: "r"(dst), "l"(src) : "memory");
}
#define CP_COMMIT() asm volatile("cp.async.commit_group;" ::: "memory")
#define CP_WAIT0()  asm volatile("cp.async.wait_group 0;" ::: "memory")

__device__ __forceinline__ float fast_tanh(float x) {
    float t = x * 2.885390081777927f;  // 2*log2(e)
    float e;
    asm("ex2.approx.f32 %0, %1;" : "=f"(e) : "f"(t));
    float r;
    asm("rcp.approx.f32 %0, %1;" : "=f"(r) : "f"(e + 1.0f));
    return 1.0f - 2.0f * r;
}
__device__ __forceinline__ float fast_exp(float x) {
    float t = x * 1.4426950408889634f;
    float e;
    asm("ex2.approx.f32 %0, %1;" : "=f"(e) : "f"(t));
    return e;
}
__device__ __forceinline__ uint32_t pack_h2(__half a, __half b) {
    __half2 v = __halves2half2(a, b);
    return *reinterpret_cast<uint32_t*>(&v);
}

// ---------------------------------------------------------------------------
// K0: fused prep. Blocks 0..511: convB row. Blocks 512..543: base[b,:].
// Block 544: worklist.
// ---------------------------------------------------------------------------
__global__ __launch_bounds__(512) void prep_kernel(
    const float* __restrict__ W1, const float* __restrict__ summary,
    const float* __restrict__ b1, const int* __restrict__ tlen) {
    int blk = blockIdx.x;
    int tid = threadIdx.x;

    if (blk < 512) {
        g_Bf[blk * 512 + tid] = __float2half_rn(W1[(size_t)blk * NC + tid]);
    } else if (blk < 544) {
        int b = blk - 512;
        __shared__ float ss[512];
        ss[tid] = summary[b * 512 + tid];
        __syncthreads();
        const float* w = W1 + (size_t)tid * NC + 512;
        float acc = b1[tid];
#pragma unroll 8
        for (int c = 0; c < 512; c++) acc += ss[c] * w[c];
        g_base[b * NH + tid] = acc;
    } else if (tid < 32) {
        int nt = (tlen[tid] + 127) >> 7;
        int off = nt;
#pragma unroll
        for (int d = 1; d < 32; d <<= 1) {
            int v = __shfl_up_sync(0xffffffffu, off, d);
            if (tid >= d) off += v;
        }
        int excl = off - nt;
        for (int t = 0; t < nt; t++) g_work[excl + t] = (tid << 5) | t;
        if (tid == 31) g_nwork = off;
    }
}

// ---------------------------------------------------------------------------
// K1: HMMA GEMM (r15 geometry: 128m x 512h, 512 threads, 16 warps 4m x 4n,
// A resident + pipelined conversion, flat 16-stage B pipeline, register
// logit partials). NEW: converted A tiles are side-written to g_Af so the
// context kernel can read fp16 (half the DRAM traffic).
// ---------------------------------------------------------------------------
__global__ __launch_bounds__(512, 1) void gemm_kernel(
    const float* __restrict__ ts, const float* __restrict__ W1,
    const float* __restrict__ W2, const float* __restrict__ coverage) {
    extern __shared__ char smem[];
    const uint32_t sb = smem_u32(smem);
    const int tid = threadIdx.x;
    const int lane = tid & 31;
    const int warp = tid >> 5;
    const int wm = warp & 3;   // m quadrant (32 rows)
    const int wn = warp >> 2;  // n quadrant (32 cols)

    if ((int)blockIdx.x >= g_nwork) return;
    const int wk = g_work[blockIdx.x];
    const int b = wk >> 5;
    const size_t m0 = (size_t)wk * MT;

    float* s_w2 = (float*)(smem + SM_TAB);            // 512
    float* s_base = (float*)(smem + SM_TAB + 2048);   // 512
    float* s_wcov = (float*)(smem + SM_TAB + 4096);   // 512
    float* s_red = (float*)(smem + SM_TAB + 6144);    // 128 x 4

    // ---- prologue: B stage 0 (async) + A chunk 0 conversion + tables ----
    {
#pragma unroll
        for (int i = 0; i < 4; i++) {
            int e = tid + i * 512;
            int r = e >> 4, c = e & 15;
            cpasync16(sb + SM_B + (uint32_t)(r * B_ROWB + c * 16),
                      g_Bf + (size_t)r * 512 + c * 8);
        }
        CP_COMMIT();

#pragma unroll
        for (int i = 0; i < 8; i++) {
            int e = tid + i * 512;
            int r = e >> 5, q = e & 31;
            float4 v = *(const float4*)(ts + (m0 + r) * 512 + q * 4);
            uint2 pk = make_uint2(
                pack_h2(__float2half_rn(v.x), __float2half_rn(v.y)),
                pack_h2(__float2half_rn(v.z), __float2half_rn(v.w)));
            *(uint2*)(smem + r * A_ROWB + q * 8) = pk;
            *(uint2*)(g_Af + (m0 + r) * 512 + q * 4) = pk;
        }

        s_w2[tid] = W2[tid];
        s_base[tid] = g_base[b * NH + tid];
        s_wcov[tid] = W1[(size_t)tid * NC + 1024];
        CP_WAIT0();
        __syncthreads();
    }

    const uint32_t aBase =
        sb + (uint32_t)((wm * 32 + (lane & 15)) * A_ROWB + (lane >> 4) * 16);
    const uint32_t bBase0 =
        sb + SM_B +
        (uint32_t)((wn * 32 + (lane & 7) + ((lane >> 4) & 1) * 8) * B_ROWB +
                   ((lane >> 3) & 1) * 16);

    float acc[2][4][4];
#pragma unroll
    for (int i = 0; i < 2; i++)
#pragma unroll
        for (int j = 0; j < 4; j++)
#pragma unroll
            for (int c = 0; c < 4; c++) acc[i][j][c] = 0.0f;

    float rsum[2][2] = {{0.0f, 0.0f}, {0.0f, 0.0f}};
    float covr[2][2];
#pragma unroll
    for (int tm = 0; tm < 2; tm++)
#pragma unroll
        for (int rh = 0; rh < 2; rh++)
            covr[tm][rh] =
                coverage[m0 + wm * 32 + tm * 16 + rh * 8 + (lane >> 2)];

    const int cr = tid >> 4;   // B cp.async row base (0..31), +32 per i
    const int ccB = tid & 15;  // 16B chunk in B row

    for (int g = 0; g < NST; g++) {
        const uint32_t bo = (uint32_t)((g & 1) * B_TILE);

        if (g < NST - 1) {
            const int gn = g + 1;
            const int htn = gn >> 2, sn = gn & 3;
            const uint32_t nbo = (uint32_t)((gn & 1) * B_TILE);
#pragma unroll
            for (int i = 0; i < 4; i++) {
                int r = cr + i * 32;
                cpasync16(sb + SM_B + nbo + (uint32_t)(r * B_ROWB + ccB * 16),
                          g_Bf + (size_t)(htn * 128 + r) * 512 + sn * 128 +
                              ccB * 8);
            }
            CP_COMMIT();
        }

        // A prefetch (first h-tile only): chunk g+1, group 0
        const bool aPre = (g < 3);
        const int acol = (g + 1) * 128;   // fp32/fp16 column base of chunk g+1
        float4 av[4];
        if (aPre) {
#pragma unroll
            for (int i = 0; i < 4; i++) {
                int e = tid + i * 512;
                int r = e >> 5, q = e & 31;
                av[i] = *(const float4*)(ts + (m0 + r) * 512 + acol + q * 4);
            }
        }

        const uint32_t aOff = (uint32_t)((g & 3) * 256);
#pragma unroll
        for (int ks = 0; ks < 4; ks++) {
            uint32_t a0, a1, a2, a3, a4, a5, a6, a7;
            ldsm4(aBase + aOff + ks * 32, a0, a1, a2, a3);
            ldsm4(aBase + aOff + ks * 32 + 16 * A_ROWB, a4, a5, a6, a7);
#pragma unroll
            for (int tp = 0; tp < 2; tp++) {
                uint32_t b0, b1, b2, b3;
                ldsm4(bBase0 + bo + ks * 32 + tp * 16 * B_ROWB, b0, b1, b2, b3);
                mma16816(acc[0][2 * tp], a0, a1, a2, a3, b0, b1);
                mma16816(acc[0][2 * tp + 1], a0, a1, a2, a3, b2, b3);
                mma16816(acc[1][2 * tp], a4, a5, a6, a7, b0, b1);
                mma16816(acc[1][2 * tp + 1], a4, a5, a6, a7, b2, b3);
            }
        }

        if (aPre) {
#pragma unroll
            for (int i = 0; i < 4; i++) {
                int e = tid + i * 512;
                int r = e >> 5, q = e & 31;
                uint2 pk = make_uint2(
                    pack_h2(__float2half_rn(av[i].x), __float2half_rn(av[i].y)),
                    pack_h2(__float2half_rn(av[i].z),
                            __float2half_rn(av[i].w)));
                *(uint2*)(smem + r * A_ROWB + acol * 2 + q * 8) = pk;
                *(uint2*)(g_Af + (m0 + r) * 512 + acol + q * 4) = pk;
            }
#pragma unroll
            for (int i = 0; i < 4; i++) {
                int e = tid + (i + 4) * 512;
                int r = e >> 5, q = e & 31;
                av[i] = *(const float4*)(ts + (m0 + r) * 512 + acol + q * 4);
            }
        }

#pragma unroll
        for (int ks = 4; ks < 8; ks++) {
            uint32_t a0, a1, a2, a3, a4, a5, a6, a7;
            ldsm4(aBase + aOff + ks * 32, a0, a1, a2, a3);
            ldsm4(aBase + aOff + ks * 32 + 16 * A_ROWB, a4, a5, a6, a7);
#pragma unroll
            for (int tp = 0; tp < 2; tp++) {
                uint32_t b0, b1, b2, b3;
                ldsm4(bBase0 + bo + ks * 32 + tp * 16 * B_ROWB, b0, b1, b2, b3);
                mma16816(acc[0][2 * tp], a0, a1, a2, a3, b0, b1);
                mma16816(acc[0][2 * tp + 1], a0, a1, a2, a3, b2, b3);
                mma16816(acc[1][2 * tp], a4, a5, a6, a7, b0, b1);
                mma16816(acc[1][2 * tp + 1], a4, a5, a6, a7, b2, b3);
            }
        }

        if (aPre) {
#pragma unroll
            for (int i = 0; i < 4; i++) {
                int e = tid + (i + 4) * 512;
                int r = e >> 5, q = e & 31;
                uint2 pk = make_uint2(
                    pack_h2(__float2half_rn(av[i].x), __float2half_rn(av[i].y)),
                    pack_h2(__float2half_rn(av[i].z),
                            __float2half_rn(av[i].w)));
                *(uint2*)(smem + r * A_ROWB + acol * 2 + q * 8) = pk;
                *(uint2*)(g_Af + (m0 + r) * 512 + acol + q * 4) = pk;
            }
        }

        if ((g & 3) == 3) {
            const int h0 = (g >> 2) * 128;
#pragma unroll
            for (int tm = 0; tm < 2; tm++) {
#pragma unroll
                for (int rh = 0; rh < 2; rh++) {
                    float cov = covr[tm][rh];
                    float rs = 0.0f;
#pragma unroll
                    for (int tn = 0; tn < 4; tn++) {
                        int h = h0 + wn * 32 + tn * 8 + (lane & 3) * 2;
                        float p0 = acc[tm][tn][rh * 2 + 0] + s_base[h] +
                                   cov * s_wcov[h];
                        float p1 = acc[tm][tn][rh * 2 + 1] + s_base[h + 1] +
                                   cov * s_wcov[h + 1];
                        rs += fast_tanh(p0) * s_w2[h] +
                              fast_tanh(p1) * s_w2[h + 1];
                    }
                    rsum[tm][rh] += rs;
#pragma unroll
                    for (int tn = 0; tn < 4; tn++) {
                        acc[tm][tn][rh * 2 + 0] = 0.0f;
                        acc[tm][tn][rh * 2 + 1] = 0.0f;
                    }
                }
            }
        }

        if (g < NST - 1) CP_WAIT0();
        __syncthreads();
    }

#pragma unroll
    for (int tm = 0; tm < 2; tm++) {
#pragma unroll
        for (int rh = 0; rh < 2; rh++) {
            float rs = rsum[tm][rh];
            rs += __shfl_xor_sync(0xffffffffu, rs, 1);
            rs += __shfl_xor_sync(0xffffffffu, rs, 2);
            int m_local = wm * 32 + tm * 16 + rh * 8 + (lane >> 2);
            if ((lane & 3) == 0) s_red[m_local * 4 + wn] = rs;
        }
    }
    __syncthreads();
    if (tid < 128)
        g_logits[m0 + tid] = (s_red[tid * 4] + s_red[tid * 4 + 1]) +
                             (s_red[tid * 4 + 2] + s_red[tid * 4 + 3]);
}

// ---------------------------------------------------------------------------
// K3: per-batch masked softmax (512 threads)
// ---------------------------------------------------------------------------
__global__ __launch_bounds__(512) void softmax_kernel(const int* __restrict__ tlen,
                                                      float* __restrict__ att_out) {
    int b = blockIdx.x;
    int tid = threadIdx.x;
    __shared__ float sl[NL];
    __shared__ float rbuf[512];
    int len = tlen[b];

    for (int l = tid; l < len; l += 512) sl[l] = g_logits[b * NL + l];
    __syncthreads();

    float mx = -INFINITY;
    for (int l = tid; l < len; l += 512) mx = fmaxf(mx, sl[l]);
    rbuf[tid] = mx;
    __syncthreads();
    for (int s = 256; s > 0; s >>= 1) {
        if (tid < s) rbuf[tid] = fmaxf(rbuf[tid], rbuf[tid + s]);
        __syncthreads();
    }
    mx = rbuf[0];
    __syncthreads();

    float sum = 0.0f;
    for (int l = tid; l < len; l += 512) {
        float e = fast_exp(sl[l] - mx);
        sl[l] = e;
        sum += e;
    }
    rbuf[tid] = sum;
    __syncthreads();
    for (int s = 256; s > 0; s >>= 1) {
        if (tid < s) rbuf[tid] = rbuf[tid] + rbuf[tid + s];
        __syncthreads();
    }
    float inv = 1.0f / rbuf[0];

    for (int l = tid; l < NL; l += 512)
        att_out[b * NL + l] = (l < len) ? sl[l] * inv : 0.0f;
}

// ---------------------------------------------------------------------------
// K4: context partials, reading fp16 g_Af (half the DRAM traffic).
// 512 threads: fq = tid&63 (8-col half group), lg = tid>>6 (16-row subgroup).
// 16 x uint4 (16B) loads per thread, batched 4-deep.
// ---------------------------------------------------------------------------
__global__ __launch_bounds__(512) void ctx_part_kernel(
    const float* __restrict__ att) {
    if ((int)blockIdx.x >= g_nwork) return;
    int wk = g_work[blockIdx.x];
    int b = wk >> 5;
    int c = wk & 31;
    int tid = threadIdx.x;
    const int fq = tid & 63;   // 8-half column group
    const int lg = tid >> 6;   // 0..7 (16 rows each)

    __shared__ float sa[128];
    __shared__ float red[8][512];
    if (tid < 128) sa[tid] = att[b * NL + c * 128 + tid];
    __syncthreads();

    const uint4* base =
        (const uint4*)(g_Af + ((size_t)b * NL + c * 128) * 512) + fq;
    float acc[8];
#pragma unroll
    for (int j = 0; j < 8; j++) acc[j] = 0.0f;

#pragma unroll
    for (int bt = 0; bt < 4; bt++) {
        const int l0 = lg * 16 + bt * 4;
        uint4 v[4];
#pragma unroll
        for (int j = 0; j < 4; j++) v[j] = base[(size_t)(l0 + j) * 64];
#pragma unroll
        for (int j = 0; j < 4; j++) {
            float w = sa[l0 + j];
            float2 f0 = __half22float2(*(__half2*)&v[j].x);
            float2 f1 = __half22float2(*(__half2*)&v[j].y);
            float2 f2 = __half22float2(*(__half2*)&v[j].z);
            float2 f3 = __half22float2(*(__half2*)&v[j].w);
            acc[0] += w * f0.x;
            acc[1] += w * f0.y;
            acc[2] += w * f1.x;
            acc[3] += w * f1.y;
            acc[4] += w * f2.x;
            acc[5] += w * f2.y;
            acc[6] += w * f3.x;
            acc[7] += w * f3.y;
        }
    }
#pragma unroll
    for (int j = 0; j < 8; j++) red[lg][fq * 8 + j] = acc[j];
    __syncthreads();

    // f = tid: sum the 8 l-subgroups
    float s = 0.0f;
#pragma unroll
    for (int g = 0; g < 8; g++) s += red[g][tid];
    g_ctx_part[((size_t)c * NB + b) * 512 + tid] = s;
}

__global__ __launch_bounds__(512) void ctx_reduce_kernel(
    const int* __restrict__ tlen, float* __restrict__ ctx) {
    int b = blockIdx.x;
    int f = threadIdx.x;
    int nt = (tlen[b] + 127) >> 7;
    float s = 0.0f;
    for (int c = 0; c < nt; c++)
        s += g_ctx_part[((size_t)c * NB + b) * 512 + f];
    ctx[b * 512 + f] = s;
}

// ---------------------------------------------------------------------------
// Launch
// ---------------------------------------------------------------------------
extern "C" void kernel_launch(void* const* d_in, const int* in_sizes, int n_in,
                              void* d_out, int out_size) {
    const float* ts  = (const float*)d_in[0];
    const float* ss  = (const float*)d_in[1];
    const float* cov = (const float*)d_in[2];
    const float* W1  = (const float*)d_in[3];
    const float* b1  = (const float*)d_in[4];
    const float* W2  = (const float*)d_in[5];
    const int*   tl  = (const int*)d_in[7];
    float* out = (float*)d_out;
    float* ctx_out = out;             // [32,512]
    float* att_out = out + NB * 512;  // [32,4096]

    cudaFuncSetAttribute(gemm_kernel,
                         cudaFuncAttributeMaxDynamicSharedMemorySize, SMEM_TOTAL);

    prep_kernel<<<545, 512>>>(W1, ss, b1, tl);
    gemm_kernel<<<1024, 512, SMEM_TOTAL>>>(ts, W1, W2, cov);
    softmax_kernel<<<NB, 512>>>(tl, att_out);
    ctx_part_kernel<<<1024, 512>>>(att_out);
    ctx_reduce_kernel<<<NB, 512>>>(tl, ctx_out);
}